// round 17
// baseline (speedup 1.0000x reference)
#include <cuda_runtime.h>
#include <cuda_bf16.h>
#include <math.h>
#include <stdint.h>

#define Bdim 128
#define Tdim 256
#define Adim 8
#define Hdim 1024
#define BT   (Bdim * Tdim)        // 32768
#define G3H  (3 * Hdim)           // 3072
#define KC   3072                 // concat K (xp gemm only)
#define KC2  2048                 // [h1|h2] / [w1|w2] width (gru)
#define NCH  48                   // K chunks of 64 (xp gemm)
#define GCH2 8                    // 128-K super-chunks (gru)

// ---------------- device scratch ----------------
__device__ float g_xp[(size_t)BT * G3H];                 // [BT,3H] fp32
__device__ __nv_bfloat16 g_Axp[(size_t)BT * KC];         // [x1|x1|x2] (xp)
__device__ __nv_bfloat16 g_Bih[(size_t)G3H * KC];        // row n: [w1|w2|w1] (xp)
__device__ __nv_bfloat16 g_Bhh[(size_t)G3H * KC2];       // row j=3i+g: [w1|w2]
__device__ __nv_bfloat16 g_Ah[2][(size_t)Bdim * KC2];    // [h1|h2] ping-pong
__device__ unsigned g_cnt4[4];                           // per-mb barrier counts
__device__ unsigned g_flag4[4];                          // per-mb barrier flags

// ---------------- helpers ----------------
__device__ __forceinline__ uint32_t smem_to_u32(const void* p) {
    uint32_t a;
    asm("{ .reg .u64 t; cvta.to.shared.u64 t, %1; cvt.u32.u64 %0, t; }" : "=r"(a) : "l"(p));
    return a;
}
__device__ __forceinline__ void ldsm4(uint32_t* r, uint32_t a) {
    asm volatile("ldmatrix.sync.aligned.m8n8.x4.shared.b16 {%0,%1,%2,%3}, [%4];"
        : "=r"(r[0]), "=r"(r[1]), "=r"(r[2]), "=r"(r[3]) : "r"(a));
}
__device__ __forceinline__ void mma16816(float* d, const uint32_t* a, const uint32_t* b) {
    asm volatile("mma.sync.aligned.m16n8k16.row.col.f32.bf16.bf16.f32 "
        "{%0,%1,%2,%3}, {%4,%5,%6,%7}, {%8,%9}, {%0,%1,%2,%3};"
        : "+f"(d[0]), "+f"(d[1]), "+f"(d[2]), "+f"(d[3])
        : "r"(a[0]), "r"(a[1]), "r"(a[2]), "r"(a[3]), "r"(b[0]), "r"(b[1]));
}
#define CP_ASYNC16(d, s) asm volatile("cp.async.cg.shared.global [%0], [%1], 16;" :: "r"(d), "l"(s))
#define CP_COMMIT()      asm volatile("cp.async.commit_group;" ::: "memory")
#define CP_WAIT1()       asm volatile("cp.async.wait_group 1;" ::: "memory")
#define CP_WAIT_ALL()    asm volatile("cp.async.wait_group 0;" ::: "memory")
#define SWZ(o) ((o) ^ (((o) >> 3) & 0x70))

// ---------------- kernel 1: proj + split (xp operand, [x1|x1|x2]) -------
__global__ __launch_bounds__(128) void proj_split(
    const float* __restrict__ actions, const float* __restrict__ fc_w,
    const float* __restrict__ fc_b)
{
    const int m = blockIdx.x, t = threadIdx.x;
    __shared__ float act[Adim];
    if (t < Adim) act[t] = actions[m * Adim + t];
    __syncthreads();
    const float a0 = act[0], a1 = act[1], a2 = act[2], a3 = act[3];
    const float a4 = act[4], a5 = act[5], a6 = act[6], a7 = act[7];
    __nv_bfloat16* dst = g_Axp + (size_t)m * KC;
#pragma unroll
    for (int j = 0; j < Hdim / 128; j++) {
        const int h = t + j * 128;
        const float4* wp = reinterpret_cast<const float4*>(fc_w + (size_t)h * Adim);
        const float4 w0 = wp[0], w1 = wp[1];
        float v = fc_b[h];
        v += a0 * w0.x + a1 * w0.y + a2 * w0.z + a3 * w0.w;
        v += a4 * w1.x + a5 * w1.y + a6 * w1.z + a7 * w1.w;
        v = fmaxf(v, 0.0f);
        const __nv_bfloat16 x1 = __float2bfloat16(v);
        const __nv_bfloat16 x2 = __float2bfloat16(v - __bfloat162float(x1));
        dst[h] = x1; dst[Hdim + h] = x1; dst[2 * Hdim + h] = x2;
    }
}

// ---------------- kernel 2: weight splits -------------------------------
__global__ __launch_bounds__(256) void split_w(
    const float* __restrict__ w_ih, const float* __restrict__ w_hh)
{
    const int bid = blockIdx.x;
    if (bid < G3H) {
        const float* src = w_ih + (size_t)bid * Hdim;
        __nv_bfloat16* dst = g_Bih + (size_t)bid * KC;
#pragma unroll
        for (int u = 0; u < Hdim / 256; u++) {
            const int k = threadIdx.x + u * 256;
            const float w = src[k];
            const __nv_bfloat16 w1 = __float2bfloat16(w);
            const __nv_bfloat16 w2 = __float2bfloat16(w - __bfloat162float(w1));
            dst[k] = w1; dst[Hdim + k] = w2; dst[2 * Hdim + k] = w1;
        }
    } else {
        const int j = bid - G3H, g = j % 3, i = j / 3;
        const float* src = w_hh + (size_t)(g * Hdim + i) * Hdim;
        __nv_bfloat16* dst = g_Bhh + (size_t)j * KC2;
#pragma unroll
        for (int u = 0; u < Hdim / 256; u++) {
            const int k = threadIdx.x + u * 256;
            const float w = src[k];
            const __nv_bfloat16 w1 = __float2bfloat16(w);
            const __nv_bfloat16 w2 = __float2bfloat16(w - __bfloat162float(w1));
            dst[k] = w1; dst[Hdim + k] = w2;
        }
    }
}

// ---------------- kernel 3: split hidden + reset barriers ---------------
__global__ __launch_bounds__(256) void split_h0(const float* __restrict__ hidden)
{
    if (blockIdx.x == 0 && threadIdx.x < 4) {
        g_cnt4[threadIdx.x] = 0; g_flag4[threadIdx.x] = 0;
    }
    const int b = blockIdx.x;
    __nv_bfloat16* dst = g_Ah[0] + (size_t)b * KC2;
    const float* src = hidden + (size_t)b * Hdim;
#pragma unroll
    for (int u = 0; u < Hdim / 256; u++) {
        const int k = threadIdx.x + u * 256;
        const float h = src[k];
        const __nv_bfloat16 h1 = __float2bfloat16(h);
        const __nv_bfloat16 h2 = __float2bfloat16(h - __bfloat162float(h1));
        dst[k] = h1; dst[Hdim + k] = h2;
    }
}

// ---------------- kernel 4: xp GEMM, 3 stages (proven R15) --------------
#define XP_STAGE 28672
#define XP_NST   3
#define XP_SMEM  (XP_NST * XP_STAGE)

__global__ __launch_bounds__(256, 2) void xp_mma(const float* __restrict__ b_ih)
{
    extern __shared__ char sm[];
    const uint32_t smb = smem_to_u32(sm);
    const int tid = threadIdx.x, lane = tid & 31, wid = tid >> 5;
    const int nb = blockIdx.x, mb = blockIdx.y;

    uint32_t sdst[7]; const char* gsrc[7];
#pragma unroll
    for (int u = 0; u < 7; u++) {
        const int sidx = tid + u * 256;
        if (sidx < 1024) {
            const int row = sidx >> 3, s8 = sidx & 7;
            sdst[u] = SWZ((uint32_t)(row * 128 + s8 * 16));
            gsrc[u] = (const char*)g_Axp + (size_t)(mb * 128 + row) * (KC * 2) + s8 * 16;
        } else {
            const int bx = sidx - 1024, row = bx >> 3, s8 = bx & 7;
            sdst[u] = 16384u + SWZ((uint32_t)(row * 128 + s8 * 16));
            gsrc[u] = (const char*)g_Bih + (size_t)(nb * 96 + row) * (KC * 2) + s8 * 16;
        }
    }
    auto prefetch = [&](int c, int st) {
        if (c < NCH) {
            const uint32_t sb = smb + (uint32_t)st * XP_STAGE;
            const size_t off = (size_t)c * 128;
#pragma unroll
            for (int u = 0; u < 7; u++) CP_ASYNC16(sb + sdst[u], gsrc[u] + off);
        }
        CP_COMMIT();
    };

    const int mrow0 = (wid & 3) * 32, nc0 = (wid >> 2) * 48;
    const uint32_t ar0 = mrow0 + (lane & 15), ar1 = ar0 + 16;
    const uint32_t aoff0 = ar0 * 128, amk0 = (ar0 & 7) << 4;
    const uint32_t aoff1 = ar1 * 128, amk1 = (ar1 & 7) << 4;
    const uint32_t akh = (uint32_t)(lane >> 4) * 16;
    uint32_t boff[3], bmk[3];
#pragma unroll
    for (int p = 0; p < 3; p++) {
        const uint32_t nr = nc0 + p * 16 + (lane >> 4) * 8 + (lane & 7);
        boff[p] = 16384u + nr * 128; bmk[p] = (nr & 7) << 4;
    }
    const uint32_t bkh = (uint32_t)((lane >> 3) & 1) * 16;

    float acc[2][6][4] = {};
    prefetch(0, 0); prefetch(1, 1);
    int sc = 0;
    for (int c = 0; c < NCH; c++) {
        CP_WAIT1();
        __syncthreads();
        {
            int sp = sc + 2; if (sp >= XP_NST) sp -= XP_NST;
            prefetch(c + 2, sp);
        }
        const uint32_t sb = smb + (uint32_t)sc * XP_STAGE;
#pragma unroll
        for (int s = 0; s < 4; s++) {
            uint32_t a0[4], a1[4], b[12];
            const uint32_t cA = akh + s * 32, cB = bkh + s * 32;
            ldsm4(a0, sb + aoff0 + (cA ^ amk0));
            ldsm4(a1, sb + aoff1 + (cA ^ amk1));
#pragma unroll
            for (int p = 0; p < 3; p++) ldsm4(b + 4 * p, sb + boff[p] + (cB ^ bmk[p]));
#pragma unroll
            for (int nt = 0; nt < 6; nt++) {
                mma16816(acc[0][nt], a0, b + 2 * nt);
                mma16816(acc[1][nt], a1, b + 2 * nt);
            }
        }
        sc++; if (sc == XP_NST) sc = 0;
    }

    const int q = lane & 3, r4 = lane >> 2;
#pragma unroll
    for (int mg = 0; mg < 2; mg++) {
        const int row = mb * 128 + mrow0 + mg * 16 + r4;
#pragma unroll
        for (int nt = 0; nt < 6; nt++) {
            const int col = nb * 96 + nc0 + nt * 8 + 2 * q;
            const float2 bias = *reinterpret_cast<const float2*>(b_ih + col);
            float2 v0, v1;
            v0.x = acc[mg][nt][0] + bias.x; v0.y = acc[mg][nt][1] + bias.y;
            v1.x = acc[mg][nt][2] + bias.x; v1.y = acc[mg][nt][3] + bias.y;
            *reinterpret_cast<float2*>(g_xp + (size_t)row * G3H + col) = v0;
            *reinterpret_cast<float2*>(g_xp + (size_t)(row + 8) * G3H + col) = v1;
        }
    }
}

// ---------------- kernel 5: persistent GRU, 128-K super-chunks ----------
// 128 CTAs (nb 0..31, mb 0..3), 512 thr. Tile 32x96, h-K=1024 in 8 super-
// chunks of 128 K-elems. Stage (64KB) = two 32KB halves, each the proven
// layout: A_h1@0 | A_h2@4K | B_w1@8K | B_w2@20K. 3-stage ring (192KB).
// 8 sync boundaries/step (was 16). Tail: An stores -> arrive -> B pre-
// issue of chunks 0,1 + out stores overlap barrier wait -> A fills.
#define GR_STAGE 65536
#define GR_NST   3
#define GR_SMEM  (GR_NST * GR_STAGE)
#define GRP 32

__global__ __launch_bounds__(512) void gru_persist(
    const float* __restrict__ hidden,
    const float* __restrict__ b_hh, float* __restrict__ out)
{
    extern __shared__ char sm[];
    const uint32_t smb = smem_to_u32(sm);
    const int tid = threadIdx.x, lane = tid & 31, wid = tid >> 5;
    const int kw = wid >> 2;                  // 0..3: s-step triple per half
    const int q  = wid & 3;                   // quad within group
    const int nb = blockIdx.x, mb = blockIdx.y;
    const int b0 = mb * 32, i0 = nb * 32;

    // ---- step-invariant load addresses (within a 32KB half) ----
    uint32_t sdstA; size_t aoffA;
    uint32_t sdstB[3]; const char* bsrcB[3];
    {
        const int hA = tid >> 8, r = (tid & 255) >> 3, s8 = tid & 7;
        sdstA = (uint32_t)(hA * 4096) + SWZ((uint32_t)(r * 128 + s8 * 16));
        aoffA = (size_t)(b0 + r) * (KC2 * 2) + hA * (Hdim * 2) + s8 * 16;
    }
#pragma unroll
    for (int u = 0; u < 3; u++) {
        const int bx = tid + u * 512;         // 0..1535
        const int hB = bx >= 768, rb = (bx - hB * 768) >> 3, s8 = bx & 7;
        sdstB[u] = (uint32_t)(8192 + hB * 12288) + SWZ((uint32_t)(rb * 128 + s8 * 16));
        bsrcB[u] = (const char*)g_Bhh + (size_t)(nb * 96 + rb) * (KC2 * 2) + hB * (Hdim * 2) + s8 * 16;
    }

    const int mrow0 = (q & 1) * 16, nc0 = (q >> 1) * 48;
    const uint32_t ar = mrow0 + (lane & 15);
    const uint32_t aoff = ar * 128, amk = (ar & 7) << 4;
    const uint32_t akh = (uint32_t)(lane >> 4) * 16;
    uint32_t boff[3], bmk[3];
#pragma unroll
    for (int p = 0; p < 3; p++) {
        const uint32_t nr = nc0 + p * 16 + (lane >> 4) * 8 + (lane & 7);
        boff[p] = nr * 128; bmk[p] = (nr & 7) << 4;
    }
    const uint32_t bkh = (uint32_t)((lane >> 3) & 1) * 16;

    // ---- step-invariant epilogue state: h and biases in regs ----
    float hv[2], bh0[2], bh1[2], bh2[2];
#pragma unroll
    for (int u = 0; u < 2; u++) {
        const int idx = tid + u * 512;
        const int b = b0 + (idx >> 5), i = i0 + (idx & 31);
        hv[u]  = hidden[(size_t)b * Hdim + i];
        bh0[u] = b_hh[i]; bh1[u] = b_hh[Hdim + i]; bh2[u] = b_hh[2 * Hdim + i];
    }

    auto issueB = [&](int c, int st) {        // B parts of super-chunk c
        const uint32_t sb = smb + (uint32_t)st * GR_STAGE;
        const size_t off = (size_t)c * 256;
#pragma unroll
        for (int hh = 0; hh < 2; hh++)
#pragma unroll
            for (int u = 0; u < 3; u++)
                CP_ASYNC16(sb + hh * 32768 + sdstB[u], bsrcB[u] + off + hh * 128);
    };
    auto issueA = [&](const char* Ab, int c, int st) {
        const uint32_t sb = smb + (uint32_t)st * GR_STAGE;
        const size_t off = (size_t)c * 256;
#pragma unroll
        for (int hh = 0; hh < 2; hh++)
            CP_ASYNC16(sb + hh * 32768 + sdstA, Ab + aoffA + off + hh * 128);
    };

    // step-0 B pre-fill for chunks 0,1 (uncommitted)
    issueB(0, 0); issueB(1, 1);

    for (int t = 0; t < Tdim; t++) {
        const char* Ab = (const char*)g_Ah[t & 1];
        float acc[6][4] = {};

        // hoisted xp loads — latency hidden by fill + mainloop
        float xr[2], xz[2], xn[2];
#pragma unroll
        for (int u = 0; u < 2; u++) {
            const int idx = tid + u * 512;
            const int b = b0 + (idx >> 5), i = i0 + (idx & 31);
            const float* xpr = g_xp + ((size_t)b * Tdim + t) * G3H;
            xr[u] = xpr[i]; xz[u] = xpr[Hdim + i]; xn[u] = xpr[2 * Hdim + i];
        }

        // A fills + commits (B of chunks 0,1 already in flight)
        issueA(Ab, 0, 0); CP_COMMIT();        // group0 = {B0,B1,A0}
        issueA(Ab, 1, 1); CP_COMMIT();        // group1 = {A1}

        int sc = 0;
        for (int c = 0; c < GCH2; c++) {
            CP_WAIT1();
            __syncthreads();
            {
                const int cp = c + 2;
                if (cp < GCH2) {
                    int sp = sc + 2; if (sp >= GR_NST) sp -= GR_NST;
                    issueB(cp, sp);
                    issueA(Ab, cp, sp);
                }
                CP_COMMIT();
            }
            const uint32_t sb = smb + (uint32_t)sc * GR_STAGE;
#pragma unroll
            for (int s2 = 0; s2 < 6; s2++) {
                const uint32_t hb = (s2 >= 3) ? 32768u : 0u;
                const int s = kw * 3 + (s2 >= 3 ? s2 - 3 : s2);   // 0..11
                const int p = s >> 2, sk = s & 3;
                const uint32_t aR = (p == 2) ? 4096u : 0u;
                const uint32_t bR = 8192u + ((p == 1) ? 12288u : 0u);
                uint32_t a[4], b[12];
                const uint32_t cA = akh + sk * 32, cB = bkh + sk * 32;
                ldsm4(a, sb + hb + aR + aoff + (cA ^ amk));
#pragma unroll
                for (int pq = 0; pq < 3; pq++)
                    ldsm4(b + 4 * pq, sb + hb + bR + boff[pq] + (cB ^ bmk[pq]));
#pragma unroll
                for (int nt = 0; nt < 6; nt++) mma16816(acc[nt], a, b + 2 * nt);
            }
            sc++; if (sc == GR_NST) sc = 0;
        }
        CP_WAIT_ALL();

        // ---- reduce the four partials via smem ----
        float* hp = reinterpret_cast<float*>(sm);  // 4 x [32][100] fp32
        __syncthreads();
        {
            float* hpk = hp + kw * 3200;
            const int q4 = lane & 3, r0 = mrow0 + (lane >> 2);
#pragma unroll
            for (int nt = 0; nt < 6; nt++) {
                const int cc = nc0 + nt * 8 + 2 * q4;
                hpk[r0 * 100 + cc]           = acc[nt][0];
                hpk[r0 * 100 + cc + 1]       = acc[nt][1];
                hpk[(r0 + 8) * 100 + cc]     = acc[nt][2];
                hpk[(r0 + 8) * 100 + cc + 1] = acc[nt][3];
            }
        }
        __syncthreads();

        // ---- gates; write An (next-step operand) FIRST ----
        float hnew[2];
        __nv_bfloat16* Abase = g_Ah[(t & 1) ^ 1];
#pragma unroll
        for (int u = 0; u < 2; u++) {
            const int idx = tid + u * 512;
            const int bl = idx >> 5, il = idx & 31;
            const int b = b0 + bl, i = i0 + il;
            const int o = bl * 100 + 3 * il;
            const float hr = hp[o + 0] + hp[3200 + o + 0] + hp[6400 + o + 0] + hp[9600 + o + 0] + bh0[u];
            const float hz = hp[o + 1] + hp[3200 + o + 1] + hp[6400 + o + 1] + hp[9600 + o + 1] + bh1[u];
            const float hn = hp[o + 2] + hp[3200 + o + 2] + hp[6400 + o + 2] + hp[9600 + o + 2] + bh2[u];
            const float rg = 1.0f / (1.0f + expf(-(xr[u] + hr)));
            const float zg = 1.0f / (1.0f + expf(-(xz[u] + hz)));
            const float ng = tanhf(xn[u] + rg * hn);
            hnew[u] = (1.0f - zg) * ng + zg * hv[u];
            hv[u] = hnew[u];
            const __nv_bfloat16 h1 = __float2bfloat16(hnew[u]);
            const __nv_bfloat16 h2 = __float2bfloat16(hnew[u] - __bfloat162float(h1));
            __nv_bfloat16* An = Abase + (size_t)b * KC2;
            An[i] = h1; An[Hdim + i] = h2;
        }
        __syncthreads();          // all An stores issued (hp reads done too)

        // arrive ASAP
        if (tid == 0) {
            __threadfence();
            const unsigned prev = atomicAdd(&g_cnt4[mb], 1u);
            if (prev == GRP - 1) {
                g_cnt4[mb] = 0;
                __threadfence();
                atomicExch(&g_flag4[mb], (unsigned)(t + 1));
            }
        }

        // overlap barrier wait: next step's B fill (chunks 0,1) + out stores
        if (t + 1 < Tdim) { issueB(0, 0); issueB(1, 1); }
#pragma unroll
        for (int u = 0; u < 2; u++) {
            const int idx = tid + u * 512;
            const int b = b0 + (idx >> 5), i = i0 + (idx & 31);
            out[((size_t)b * Tdim + t) * Hdim + i] = hnew[u];
        }

        // wait for the group's An writes
        if (tid == 0) {
            while (atomicAdd(&g_flag4[mb], 0u) < (unsigned)(t + 1))
                __nanosleep(32);
            __threadfence();
        }
        __syncthreads();
    }
}

// ---------------------------------------------------------------------------
extern "C" void kernel_launch(void* const* d_in, const int* in_sizes, int n_in,
                              void* d_out, int out_size)
{
    const float* actions = (const float*)d_in[0];
    const float* hidden  = (const float*)d_in[1];
    const float* fc_w    = (const float*)d_in[2];
    const float* fc_b    = (const float*)d_in[3];
    const float* w_ih    = (const float*)d_in[4];
    const float* w_hh    = (const float*)d_in[5];
    const float* b_ih    = (const float*)d_in[6];
    const float* b_hh    = (const float*)d_in[7];
    float* out = (float*)d_out;

    static bool attr_set = false;
    if (!attr_set) {
        cudaFuncSetAttribute(xp_mma, cudaFuncAttributeMaxDynamicSharedMemorySize, XP_SMEM);
        cudaFuncSetAttribute(gru_persist, cudaFuncAttributeMaxDynamicSharedMemorySize, GR_SMEM);
        attr_set = true;
    }

    proj_split<<<BT, 128>>>(actions, fc_w, fc_b);
    split_w<<<2 * G3H, 256>>>(w_ih, w_hh);
    split_h0<<<Bdim, 256>>>(hidden);
    xp_mma<<<dim3(32, 256), 256, XP_SMEM>>>(b_ih);
    gru_persist<<<dim3(32, 4), 512, GR_SMEM>>>(hidden, b_hh, out);
}